// round 8
// baseline (speedup 1.0000x reference)
#include <cuda_runtime.h>
#include <cuda_bf16.h>
#include <cstdint>

// Problem constants
#define B_  64
#define C_  2048
#define HW_ 192            // 24 * 8
#define HW4_ 48            // HW_/4 float4s per row
#define NCHUNK 32          // C chunks  (grid = 64*32 = 2048 blocks)
#define CCHUNK (C_ / NCHUNK)   // 64 channels per chunk
#define NPART (NCHUNK * 4)     // 128 partials per (b,hw)
#define NUM_IDS_ 751

// Scratch (__device__ globals; no allocation allowed)
__device__ float g_partial[B_ * NPART * HW_];    // [b][part][hw]  (6 MB)
__device__ float g_heat[B_ * HW_];               // normalized heat

// ---------------------------------------------------------------------------
// pid loader: pids buffer may be int32 (64 ints) or int64 (64 longs).
// Only the first 64 int32 words are read (256 B, safe under both layouts).
// int64 layout => odd words all 0 (values < 751); int32 => odd words random.
// ---------------------------------------------------------------------------
__device__ __forceinline__ int load_pid(const int* __restrict__ p32, int b)
{
    bool odd_all_zero = true;
    bool any_nonzero  = false;
    #pragma unroll
    for (int i = 0; i < 64; i += 2) {
        if (p32[i + 1] != 0) odd_all_zero = false;
        if (p32[i]     != 0) any_nonzero = true;
    }
    const bool is64 = odd_all_zero && any_nonzero;
    int pid = is64 ? p32[2 * b] : p32[b];
    if (pid < 0) pid = 0;
    if (pid >= NUM_IDS_) pid = NUM_IDS_ - 1;
    return pid;
}

// ---------------------------------------------------------------------------
// Kernel 1: partial heat with float4 row loads (default cache policy so f
// populates L2 for the scale kernel's re-read).
// grid = (B_, NCHUNK), block = 192 threads = 4 c-lanes x 48 float4-lanes.
// ---------------------------------------------------------------------------
__global__ void __launch_bounds__(HW_) heat_partial_kernel(
    const float4* __restrict__ f4,
    const float*  __restrict__ w,
    const int*    __restrict__ pids32)
{
    const int b     = blockIdx.x;
    const int chunk = blockIdx.y;
    const int tid   = threadIdx.x;
    const int c_sub = tid / HW4_;   // 0..3
    const int q     = tid % HW4_;   // 0..47 (float4 index within row)

    __shared__ float ws[CCHUNK];
    __shared__ int s_pid;

    if (tid == 0)
        s_pid = load_pid(pids32, b);
    __syncthreads();

    const float* wrow = w + (size_t)s_pid * C_ + chunk * CCHUNK;
    if (tid < CCHUNK)
        ws[tid] = wrow[tid];
    __syncthreads();

    const float4* fb = f4 + ((size_t)b * C_ + (size_t)chunk * CCHUNK) * HW4_ + q;

    float4 acc = make_float4(0.f, 0.f, 0.f, 0.f);
    #pragma unroll
    for (int c = c_sub; c < CCHUNK; c += 4) {
        const float4 v = fb[(size_t)c * HW4_];
        const float  s = ws[c];
        acc.x = fmaf(s, v.x, acc.x);
        acc.y = fmaf(s, v.y, acc.y);
        acc.z = fmaf(s, v.z, acc.z);
        acc.w = fmaf(s, v.w, acc.w);
    }

    const int part = chunk * 4 + c_sub;   // 0..127
    float4* gp4 = reinterpret_cast<float4*>(g_partial);
    // evict-first: partials are consumed once by heat_norm; don't evict f
    __stcs(&gp4[((size_t)b * NPART + part) * HW4_ + q], acc);
}

// ---------------------------------------------------------------------------
// Kernel 2: reduce 128 partials, min/max-normalize per b. grid = B_, block=192.
// Reads partials newest-first (reverse order) for better L2 hit rate.
// ---------------------------------------------------------------------------
__global__ void __launch_bounds__(HW_) heat_norm_kernel()
{
    const int b  = blockIdx.x;
    const int hw = threadIdx.x;

    float s0 = 0.f, s1 = 0.f, s2 = 0.f, s3 = 0.f;
    #pragma unroll
    for (int p = NPART - 4; p >= 0; p -= 4) {
        s0 += __ldcs(&g_partial[((size_t)b * NPART + p + 0) * HW_ + hw]);
        s1 += __ldcs(&g_partial[((size_t)b * NPART + p + 1) * HW_ + hw]);
        s2 += __ldcs(&g_partial[((size_t)b * NPART + p + 2) * HW_ + hw]);
        s3 += __ldcs(&g_partial[((size_t)b * NPART + p + 3) * HW_ + hw]);
    }
    const float s = (s0 + s1) + (s2 + s3);

    // block min/max over 192 values (6 warps)
    float mn = s, mx = s;
    #pragma unroll
    for (int off = 16; off > 0; off >>= 1) {
        mn = fminf(mn, __shfl_down_sync(0xffffffffu, mn, off));
        mx = fmaxf(mx, __shfl_down_sync(0xffffffffu, mx, off));
    }
    __shared__ float smn[6], smx[6];
    __shared__ float bmn, bmx;
    const int warp = hw >> 5, lane = hw & 31;
    if (lane == 0) { smn[warp] = mn; smx[warp] = mx; }
    __syncthreads();
    if (hw == 0) {
        float m0 = smn[0], m1 = smx[0];
        #pragma unroll
        for (int i = 1; i < 6; i++) {
            m0 = fminf(m0, smn[i]);
            m1 = fmaxf(m1, smx[i]);
        }
        bmn = m0; bmx = m1;
    }
    __syncthreads();

    float h = s;
    if (bmx != 0.f)
        h = (s - bmn) / (bmx - bmn);
    g_heat[(size_t)b * HW_ + hw] = h;
}

// ---------------------------------------------------------------------------
// Kernel 3: out = f * heat[b][hw], float4 + ILP4, REVERSED block order.
// heat_partial streamed f ascending; reading descending consumes the
// most-recently-cached lines first (LRU stack property) -> max L2 hits.
// __ldcs: last-use read. __stcs: streaming write, don't evict f.
// ---------------------------------------------------------------------------
#define SC_ILP 4
__global__ void __launch_bounds__(256) scale_kernel(
    const float4* __restrict__ f4,
    float4* __restrict__ out4)
{
    // reverse block order: block 0 handles the HIGHEST addresses
    const int rb   = gridDim.x - 1 - blockIdx.x;
    const int base = rb * (256 * SC_ILP) + threadIdx.x;

    float4 v[SC_ILP];
    float4 hv[SC_ILP];
    #pragma unroll
    for (int k = 0; k < SC_ILP; k++) {
        const int i  = base + k * 256;
        const int e  = i * 4;            // element index (max 25.2M, fits int32)
        const int hw = e % HW_;          // 4-aligned
        const int b  = e / (C_ * HW_);
        v[k]  = __ldcs(&f4[i]);
        hv[k] = *reinterpret_cast<const float4*>(&g_heat[b * HW_ + hw]);
    }
    #pragma unroll
    for (int k = 0; k < SC_ILP; k++) {
        const int i = base + k * 256;
        float4 r;
        r.x = v[k].x * hv[k].x;
        r.y = v[k].y * hv[k].y;
        r.z = v[k].z * hv[k].z;
        r.w = v[k].w * hv[k].w;
        __stcs(&out4[i], r);
    }
}

// ---------------------------------------------------------------------------
extern "C" void kernel_launch(void* const* d_in, const int* in_sizes, int n_in,
                              void* d_out, int out_size)
{
    // Resolve inputs by element count:
    //   features_map      : 25,165,824
    //   classifier_weight :  1,538,048
    //   pids              : 64
    const float* f = nullptr;
    const float* w = nullptr;
    const int*   p = nullptr;
    for (int i = 0; i < n_in; i++) {
        if      (in_sizes[i] == 25165824) f = (const float*)d_in[i];
        else if (in_sizes[i] == 1538048)  w = (const float*)d_in[i];
        else if (in_sizes[i] == 64)       p = (const int*)d_in[i];
    }
    float* out = (float*)d_out;

    heat_partial_kernel<<<dim3(B_, NCHUNK), HW_>>>((const float4*)f, w, p);
    heat_norm_kernel<<<B_, HW_>>>();

    const int n4 = (B_ * C_ * HW_) / 4;                  // 6,291,456
    const int blocks = n4 / (256 * SC_ILP);              // 6144 (exact)
    scale_kernel<<<blocks, 256>>>((const float4*)f, (float4*)out);
}

// round 9
// speedup vs baseline: 1.0868x; 1.0868x over previous
#include <cuda_runtime.h>
#include <cuda_bf16.h>
#include <cstdint>

// Problem constants
#define B_  64
#define C_  2048
#define HW_ 192            // 24 * 8
#define HW4_ 48            // HW_/4 float4s per row
#define NCHUNK 32          // C chunks  (grid = 64*32 = 2048 blocks)
#define CCHUNK (C_ / NCHUNK)   // 64 channels per chunk
#define NPART NCHUNK           // 32 partials per (b,hw) after smem reduction
#define NUM_IDS_ 751

// Scratch (__device__ globals; no allocation allowed)
__device__ float g_partial[B_ * NPART * HW_];    // [b][part][hw]  (1.5 MB)
__device__ float g_heat[B_ * HW_];               // normalized heat

// ---------------------------------------------------------------------------
// pid loader: pids buffer may be int32 (64 ints) or int64 (64 longs).
// Only the first 64 int32 words are read (256 B, safe under both layouts).
// int64 layout => odd words all 0 (values < 751); int32 => odd words random.
// ---------------------------------------------------------------------------
__device__ __forceinline__ int load_pid(const int* __restrict__ p32, int b)
{
    bool odd_all_zero = true;
    bool any_nonzero  = false;
    #pragma unroll
    for (int i = 0; i < 64; i += 2) {
        if (p32[i + 1] != 0) odd_all_zero = false;
        if (p32[i]     != 0) any_nonzero = true;
    }
    const bool is64 = odd_all_zero && any_nonzero;
    int pid = is64 ? p32[2 * b] : p32[b];
    if (pid < 0) pid = 0;
    if (pid >= NUM_IDS_) pid = NUM_IDS_ - 1;
    return pid;
}

// ---------------------------------------------------------------------------
// Kernel 1: partial heat, batched float4 loads (4 independent LDG.128 per
// group -> MLP_p1 >= 4), then intra-block c_sub reduction in smem.
// grid = (B_, NCHUNK), block = 192 threads = 4 c-lanes x 48 float4-lanes.
// Each thread: 16 loads in 4 groups of 4.
// ---------------------------------------------------------------------------
__global__ void __launch_bounds__(HW_) heat_partial_kernel(
    const float4* __restrict__ f4,
    const float*  __restrict__ w,
    const int*    __restrict__ pids32)
{
    const int b     = blockIdx.x;
    const int chunk = blockIdx.y;
    const int tid   = threadIdx.x;
    const int c_sub = tid / HW4_;   // 0..3
    const int q     = tid % HW4_;   // 0..47 (float4 index within row)

    __shared__ float  ws[CCHUNK];
    __shared__ float4 sred[HW_];
    __shared__ int s_pid;

    if (tid == 0)
        s_pid = load_pid(pids32, b);
    __syncthreads();

    const float* wrow = w + (size_t)s_pid * C_ + chunk * CCHUNK;
    if (tid < CCHUNK)
        ws[tid] = wrow[tid];
    __syncthreads();

    // thread covers c = c_sub + j*4, j = 0..15 ; grouped 4 at a time
    const float4* fb = f4 + ((size_t)b * C_ + (size_t)chunk * CCHUNK + c_sub) * HW4_ + q;

    float4 acc = make_float4(0.f, 0.f, 0.f, 0.f);
    #pragma unroll
    for (int g = 0; g < 4; g++) {
        // batch 4 independent 16B loads (front-batched MLP)
        float4 v0 = fb[(size_t)(g * 16 + 0) * HW4_];
        float4 v1 = fb[(size_t)(g * 16 + 4) * HW4_];
        float4 v2 = fb[(size_t)(g * 16 + 8) * HW4_];
        float4 v3 = fb[(size_t)(g * 16 + 12) * HW4_];
        const float s0 = ws[c_sub + g * 16 + 0];
        const float s1 = ws[c_sub + g * 16 + 4];
        const float s2 = ws[c_sub + g * 16 + 8];
        const float s3 = ws[c_sub + g * 16 + 12];
        acc.x = fmaf(s0, v0.x, acc.x); acc.y = fmaf(s0, v0.y, acc.y);
        acc.z = fmaf(s0, v0.z, acc.z); acc.w = fmaf(s0, v0.w, acc.w);
        acc.x = fmaf(s1, v1.x, acc.x); acc.y = fmaf(s1, v1.y, acc.y);
        acc.z = fmaf(s1, v1.z, acc.z); acc.w = fmaf(s1, v1.w, acc.w);
        acc.x = fmaf(s2, v2.x, acc.x); acc.y = fmaf(s2, v2.y, acc.y);
        acc.z = fmaf(s2, v2.z, acc.z); acc.w = fmaf(s2, v2.w, acc.w);
        acc.x = fmaf(s3, v3.x, acc.x); acc.y = fmaf(s3, v3.y, acc.y);
        acc.z = fmaf(s3, v3.z, acc.z); acc.w = fmaf(s3, v3.w, acc.w);
    }
    sred[tid] = acc;
    __syncthreads();

    // reduce 4 c_sub lanes -> one partial per (b, chunk, hw)
    if (tid < HW4_) {
        float4 t = sred[tid];
        const float4 u1 = sred[HW4_ + tid];
        const float4 u2 = sred[2 * HW4_ + tid];
        const float4 u3 = sred[3 * HW4_ + tid];
        t.x += u1.x + u2.x + u3.x;
        t.y += u1.y + u2.y + u3.y;
        t.z += u1.z + u2.z + u3.z;
        t.w += u1.w + u2.w + u3.w;
        float4* gp4 = reinterpret_cast<float4*>(g_partial);
        __stcs(&gp4[((size_t)b * NPART + chunk) * HW4_ + tid], t);
    }
}

// ---------------------------------------------------------------------------
// Kernel 2: reduce 32 partials (1.5 MB, L2-hot), min/max-normalize per b.
// grid = B_, block = 192.
// ---------------------------------------------------------------------------
__global__ void __launch_bounds__(HW_) heat_norm_kernel()
{
    const int b  = blockIdx.x;
    const int hw = threadIdx.x;

    float s0 = 0.f, s1 = 0.f, s2 = 0.f, s3 = 0.f;
    #pragma unroll
    for (int p = 0; p < NPART; p += 4) {
        s0 += __ldcs(&g_partial[((size_t)b * NPART + p + 0) * HW_ + hw]);
        s1 += __ldcs(&g_partial[((size_t)b * NPART + p + 1) * HW_ + hw]);
        s2 += __ldcs(&g_partial[((size_t)b * NPART + p + 2) * HW_ + hw]);
        s3 += __ldcs(&g_partial[((size_t)b * NPART + p + 3) * HW_ + hw]);
    }
    const float s = (s0 + s1) + (s2 + s3);

    // block min/max over 192 values (6 warps)
    float mn = s, mx = s;
    #pragma unroll
    for (int off = 16; off > 0; off >>= 1) {
        mn = fminf(mn, __shfl_down_sync(0xffffffffu, mn, off));
        mx = fmaxf(mx, __shfl_down_sync(0xffffffffu, mx, off));
    }
    __shared__ float smn[6], smx[6];
    __shared__ float bmn, bmx;
    const int warp = hw >> 5, lane = hw & 31;
    if (lane == 0) { smn[warp] = mn; smx[warp] = mx; }
    __syncthreads();
    if (hw == 0) {
        float m0 = smn[0], m1 = smx[0];
        #pragma unroll
        for (int i = 1; i < 6; i++) {
            m0 = fminf(m0, smn[i]);
            m1 = fmaxf(m1, smx[i]);
        }
        bmn = m0; bmx = m1;
    }
    __syncthreads();

    float h = s;
    if (bmx != 0.f)
        h = (s - bmn) / (bmx - bmn);
    g_heat[(size_t)b * HW_ + hw] = h;
}

// ---------------------------------------------------------------------------
// Kernel 3: out = f * heat[b][hw], float4 + ILP4. At the HBM ceiling
// (~6.9 TB/s) -- unchanged from R7 (cache hints kept: they bought 2.4 us).
// ---------------------------------------------------------------------------
#define SC_ILP 4
__global__ void __launch_bounds__(256) scale_kernel(
    const float4* __restrict__ f4,
    float4* __restrict__ out4)
{
    const int base = blockIdx.x * (256 * SC_ILP) + threadIdx.x;

    float4 v[SC_ILP];
    float4 hv[SC_ILP];
    #pragma unroll
    for (int k = 0; k < SC_ILP; k++) {
        const int i  = base + k * 256;
        const int e  = i * 4;            // element index (max 25.2M, fits int32)
        const int hw = e % HW_;          // 4-aligned
        const int b  = e / (C_ * HW_);
        v[k]  = __ldcs(&f4[i]);
        hv[k] = *reinterpret_cast<const float4*>(&g_heat[b * HW_ + hw]);
    }
    #pragma unroll
    for (int k = 0; k < SC_ILP; k++) {
        const int i = base + k * 256;
        float4 r;
        r.x = v[k].x * hv[k].x;
        r.y = v[k].y * hv[k].y;
        r.z = v[k].z * hv[k].z;
        r.w = v[k].w * hv[k].w;
        __stcs(&out4[i], r);
    }
}

// ---------------------------------------------------------------------------
extern "C" void kernel_launch(void* const* d_in, const int* in_sizes, int n_in,
                              void* d_out, int out_size)
{
    // Resolve inputs by element count:
    //   features_map      : 25,165,824
    //   classifier_weight :  1,538,048
    //   pids              : 64
    const float* f = nullptr;
    const float* w = nullptr;
    const int*   p = nullptr;
    for (int i = 0; i < n_in; i++) {
        if      (in_sizes[i] == 25165824) f = (const float*)d_in[i];
        else if (in_sizes[i] == 1538048)  w = (const float*)d_in[i];
        else if (in_sizes[i] == 64)       p = (const int*)d_in[i];
    }
    float* out = (float*)d_out;

    heat_partial_kernel<<<dim3(B_, NCHUNK), HW_>>>((const float4*)f, w, p);
    heat_norm_kernel<<<B_, HW_>>>();

    const int n4 = (B_ * C_ * HW_) / 4;                  // 6,291,456
    const int blocks = n4 / (256 * SC_ILP);              // 6144 (exact)
    scale_kernel<<<blocks, 256>>>((const float4*)f, (float4*)out);
}